// round 3
// baseline (speedup 1.0000x reference)
#include <cuda_runtime.h>

#define NN 20000
#define EE 320000
#define GG 256
#define N2 (2 * NN)
#define E2 (2 * EE)

// -------- scratch (static device globals; zero-initialized, no runtime allocation) --------
__device__ float g_bufA[N2 * 320];   // padded node features (pad cols stay 0 forever)
__device__ float g_bufB[N2 * 320];
__device__ int   g_work[2 * N2];     // [0,N2): cnt, [N2,2*N2): fill
__device__ int   g_offs[N2 + 1];
__device__ int   g_csr[E2];
__device__ float g_dinv[N2];
__device__ float g_pool[2 * GG * 312];
__device__ float g_xc[GG * 512];
__device__ float g_t0[2 * GG * 2048];
__device__ float g_t1[2 * GG * 2048];
__device__ float g_part[8 * GG * 1024];

// -------- CSR build over combined graph (branch-1 nodes offset by NN) --------
__global__ void k_count2(const int* __restrict__ ei1, const int* __restrict__ ei2,
                         int* __restrict__ cnt) {
    int e = blockIdx.x * blockDim.x + threadIdx.x;
    if (e < EE) atomicAdd(&cnt[ei1[EE + e]], 1);
    else if (e < E2) atomicAdd(&cnt[ei2[EE + (e - EE)] + NN], 1);
}

__global__ void k_scan_dinv(const int* __restrict__ cnt, int* __restrict__ offs,
                            float* __restrict__ dinv) {
    const int T = 1024;
    const int IPT = (N2 + T - 1) / T;  // 40
    __shared__ int s[T];
    int tid = threadIdx.x;
    int base = tid * IPT;
    int local = 0;
    #pragma unroll
    for (int i = 0; i < IPT; i++) {
        int idx = base + i;
        if (idx < N2) {
            int c = cnt[idx];
            local += c;
            dinv[idx] = rsqrtf((float)(c + 1));  // +1 self loop
        }
    }
    s[tid] = local;
    __syncthreads();
    for (int off = 1; off < T; off <<= 1) {
        int v = 0;
        if (tid >= off) v = s[tid - off];
        __syncthreads();
        if (tid >= off) s[tid] += v;
        __syncthreads();
    }
    int run = (tid == 0) ? 0 : s[tid - 1];
    #pragma unroll
    for (int i = 0; i < IPT; i++) {
        int idx = base + i;
        if (idx < N2) { offs[idx] = run; run += cnt[idx]; }
    }
    if (tid == 0) offs[N2] = s[T - 1];
}

__global__ void k_fill2(const int* __restrict__ ei1, const int* __restrict__ ei2,
                        const int* __restrict__ offs, int* __restrict__ fill,
                        int* __restrict__ csr) {
    int e = blockIdx.x * blockDim.x + threadIdx.x;
    int s, d;
    if (e < EE) { s = ei1[e]; d = ei1[EE + e]; }
    else if (e < E2) { s = ei2[e - EE] + NN; d = ei2[EE + (e - EE)] + NN; }
    else return;
    int p = atomicAdd(&fill[d], 1);
    csr[offs[d] + p] = s;
}

// -------- aggregation over combined graph. dual base pointers for layer-1 (x1/x2). --------
template <int DIM, int LDI, int LDO, int R>
__global__ void k_agg(const float* __restrict__ h0, const float* __restrict__ h1,
                      const int* __restrict__ offs, const int* __restrict__ csr,
                      const float* __restrict__ dinv, float* __restrict__ out) {
    int warp = (blockIdx.x * blockDim.x + threadIdx.x) >> 5;
    int lane = threadIdx.x & 31;
    if (warp >= N2) return;
    int n = warp;
    const float* hn = (n < NN) ? h0 + (size_t)n * LDI : h1 + (size_t)(n - NN) * LDI;
    float din = dinv[n];
    float acc[R];
    #pragma unroll
    for (int r = 0; r < R; r++) {
        int f = lane + 32 * r;
        acc[r] = (f < DIM) ? din * hn[f] : 0.f;
    }
    int e0 = offs[n], e1 = offs[n + 1];
    for (int e = e0; e < e1; e++) {
        int s = csr[e];
        const float* hs = (s < NN) ? h0 + (size_t)s * LDI : h1 + (size_t)(s - NN) * LDI;
        float ds = dinv[s];
        #pragma unroll
        for (int r = 0; r < R; r++) {
            int f = lane + 32 * r;
            if (f < DIM) acc[r] += ds * hs[f];
        }
    }
    #pragma unroll
    for (int r = 0; r < R; r++) {
        int f = lane + 32 * r;
        if (f < DIM) out[(size_t)n * LDO + f] = din * acc[r];
    }
}

// -------- global max pool over combined nodes -> pool[2*G, 312] --------
__global__ void k_pool(const float* __restrict__ h,
                       const int* __restrict__ bat1, const int* __restrict__ bat2,
                       float* __restrict__ pool) {
    const int CH = 32;                    // 20000 % 32 == 0: chunks never straddle branches
    const int NCH = N2 / CH;              // 1250
    int idx = blockIdx.x * blockDim.x + threadIdx.x;
    if (idx >= NCH * 312) return;
    int f = idx % 312;
    int c = idx / 312;
    int n0 = c * CH;
    int n1 = n0 + CH;
    int curb = (n0 < NN) ? bat1[n0] : GG + bat2[n0 - NN];
    float m = 0.f;
    for (int n = n0; n < n1; n++) {
        int b = (n < NN) ? bat1[n] : GG + bat2[n - NN];
        if (b != curb) {
            atomicMax((int*)&pool[curb * 312 + f], __float_as_int(m));
            curb = b;
            m = 0.f;
        }
        m = fmaxf(m, h[(size_t)n * 312 + f]);
    }
    atomicMax((int*)&pool[curb * 312 + f], __float_as_int(m));
}

// -------- scatter branch-MLP output [2G,128] -> xc[G,512] cols [br*128, br*128+128) --------
__global__ void k_scatter(const float* __restrict__ t, float* __restrict__ xc) {
    int i = blockIdx.x * blockDim.x + threadIdx.x;
    if (i >= 2 * GG * 128) return;
    int r = i >> 7, j = i & 127;
    int br = r >> 8;       // /GG
    int g = r & 255;       // %GG
    xc[g * 512 + br * 128 + j] = t[i];
}

// -------- L2 row normalize --------
__global__ void k_norm(const float* __restrict__ cell, float* __restrict__ out) {
    int g = blockIdx.x;
    __shared__ float s[256];
    float ss = 0.f;
    for (int j = threadIdx.x; j < 954; j += 256) {
        float v = cell[g * 954 + j];
        ss += v * v;
    }
    s[threadIdx.x] = ss;
    __syncthreads();
    for (int o = 128; o > 0; o >>= 1) {
        if (threadIdx.x < o) s[threadIdx.x] += s[threadIdx.x + o];
        __syncthreads();
    }
    float inv = 1.f / fmaxf(sqrtf(s[0]), 1e-12f);
    for (int j = threadIdx.x; j < 954; j += 256)
        out[g * 954 + j] = cell[g * 954 + j] * inv;
}

// -------- node SGEMM: 128x128 tiles, BK=8, double-buffered, 8x8/thread.
// A reads are UNGUARDED float4 within padded lda (pad cols/rows of bufA are always 0).
template <bool RELU>
__global__ __launch_bounds__(256)
void k_gemm128(const float* __restrict__ A, int lda,
               const float* __restrict__ B,
               const float* __restrict__ bias,
               float* __restrict__ C, int ldc,
               int M, int N, int K) {
    const int BK = 8;
    __shared__ float As[2][BK][128];
    __shared__ float Bs[2][BK][128];
    int m0 = blockIdx.y * 128;
    int n0 = blockIdx.x * 128;
    int tid = threadIdx.x;
    int tx = tid & 15, ty = tid >> 4;
    int ar = tid & 127, ak = (tid >> 7) << 2;   // A: row ar, k-offset 0 or 4
    int brr = tid >> 5, bc = tid & 31;          // B: k-row 0..7, col base 0..31

    const float* Aptr = A + (size_t)(m0 + ar) * lda;
    int ktiles = (K + BK - 1) / BK;
    float acc[8][8] = {};

    {   // prologue: tile 0 -> buffer 0
        float4 av = *(const float4*)(Aptr + ak);
        As[0][ak + 0][ar] = av.x; As[0][ak + 1][ar] = av.y;
        As[0][ak + 2][ar] = av.z; As[0][ak + 3][ar] = av.w;
        #pragma unroll
        for (int i = 0; i < 4; i++) {
            int nn = n0 + bc + 32 * i;
            Bs[0][brr][bc + 32 * i] = (brr < K && nn < N) ? B[brr * N + nn] : 0.f;
        }
    }
    __syncthreads();

    for (int t = 0; t < ktiles; t++) {
        int cur = t & 1;
        bool more = (t + 1 < ktiles);
        float4 av;
        float bv[4];
        if (more) {
            int k0 = (t + 1) * BK;
            av = *(const float4*)(Aptr + k0 + ak);
            #pragma unroll
            for (int i = 0; i < 4; i++) {
                int kk = k0 + brr, nn = n0 + bc + 32 * i;
                bv[i] = (kk < K && nn < N) ? B[kk * N + nn] : 0.f;
            }
        }
        #pragma unroll
        for (int k = 0; k < BK; k++) {
            float a[8], b[8];
            #pragma unroll
            for (int i = 0; i < 8; i++) a[i] = As[cur][k][ty * 8 + i];
            #pragma unroll
            for (int j = 0; j < 8; j++) b[j] = Bs[cur][k][tx * 8 + j];
            #pragma unroll
            for (int i = 0; i < 8; i++)
                #pragma unroll
                for (int j = 0; j < 8; j++) acc[i][j] += a[i] * b[j];
        }
        if (more) {
            int nxt = cur ^ 1;
            As[nxt][ak + 0][ar] = av.x; As[nxt][ak + 1][ar] = av.y;
            As[nxt][ak + 2][ar] = av.z; As[nxt][ak + 3][ar] = av.w;
            #pragma unroll
            for (int i = 0; i < 4; i++) Bs[nxt][brr][bc + 32 * i] = bv[i];
            __syncthreads();
        }
    }

    #pragma unroll
    for (int i = 0; i < 8; i++) {
        int mm = m0 + ty * 8 + i;
        if (mm >= M) continue;
        #pragma unroll
        for (int j = 0; j < 8; j++) {
            int nn = n0 + tx * 8 + j;
            if (nn >= N) continue;
            float v = acc[i][j] + bias[nn];
            if (RELU) v = fmaxf(v, 0.f);
            C[(size_t)mm * ldc + nn] = v;
        }
    }
}

static void gemm_node(const float* A, int lda, const float* B, const float* bias,
                      float* C, int ldc, int M, int N, int K, bool relu) {
    dim3 grid((N + 127) / 128, (M + 127) / 128);
    if (relu) k_gemm128<true><<<grid, 256>>>(A, lda, B, bias, C, ldc, M, N, K);
    else      k_gemm128<false><<<grid, 256>>>(A, lda, B, bias, C, ldc, M, N, K);
}

// -------- small SGEMM (64x64, BK=16) with optional split-K --------
template <bool RELU, bool PARTIAL>
__global__ void k_sgemm64(const float* __restrict__ A, int lda,
                          const float* __restrict__ B,
                          const float* __restrict__ bias,
                          float* __restrict__ C, int ldc,
                          int M, int N, int K, int Kc) {
    const int BM = 64, BN = 64, BK = 16;
    __shared__ float As[BK][BM];
    __shared__ float Bs[BK][BN];
    int m0 = blockIdx.y * BM;
    int n0 = blockIdx.x * BN;
    int s  = blockIdx.z;
    int kbeg = PARTIAL ? s * Kc : 0;
    int kend = PARTIAL ? min(K, kbeg + Kc) : K;
    int tid = threadIdx.x;
    int tx = tid & 15, ty = tid >> 4;
    float acc[4][4] = {};
    for (int k0 = kbeg; k0 < kend; k0 += BK) {
        #pragma unroll
        for (int i = 0; i < 4; i++) {
            int l = tid + 256 * i;
            int r = l >> 4, c = l & 15;
            int mm = m0 + r, kk = k0 + c;
            As[c][r] = (mm < M && kk < kend) ? A[mm * lda + kk] : 0.f;
        }
        #pragma unroll
        for (int i = 0; i < 4; i++) {
            int l = tid + 256 * i;
            int r = l >> 6, c = l & 63;
            int kk = k0 + r, nn = n0 + c;
            Bs[r][c] = (kk < kend && nn < N) ? B[kk * N + nn] : 0.f;
        }
        __syncthreads();
        #pragma unroll
        for (int kk = 0; kk < BK; kk++) {
            float a[4], b[4];
            #pragma unroll
            for (int i = 0; i < 4; i++) a[i] = As[kk][ty * 4 + i];
            #pragma unroll
            for (int j = 0; j < 4; j++) b[j] = Bs[kk][tx * 4 + j];
            #pragma unroll
            for (int i = 0; i < 4; i++)
                #pragma unroll
                for (int j = 0; j < 4; j++) acc[i][j] += a[i] * b[j];
        }
        __syncthreads();
    }
    #pragma unroll
    for (int i = 0; i < 4; i++) {
        int mm = m0 + ty * 4 + i;
        if (mm >= M) continue;
        #pragma unroll
        for (int j = 0; j < 4; j++) {
            int nn = n0 + tx * 4 + j;
            if (nn >= N) continue;
            if (PARTIAL) {
                C[(size_t)s * M * N + mm * N + nn] = acc[i][j];
            } else {
                float v = acc[i][j] + bias[nn];
                if (RELU) v = fmaxf(v, 0.f);
                C[mm * ldc + nn] = v;
            }
        }
    }
}

template <bool RELU>
__global__ void k_reduce(const float* __restrict__ part, int S,
                         const float* __restrict__ bias,
                         float* __restrict__ C, int ldc, int M, int N) {
    int i = blockIdx.x * blockDim.x + threadIdx.x;
    if (i >= M * N) return;
    int m = i / N, n = i % N;
    float v = 0.f;
    for (int s = 0; s < S; s++) v += part[(size_t)s * M * N + i];
    v += bias[n];
    if (RELU) v = fmaxf(v, 0.f);
    C[m * ldc + n] = v;
}

static void sgemm_split(const float* A, int lda, const float* B, const float* bias,
                        float* C, int ldc, int M, int N, int K, int S, bool relu,
                        float* part) {
    int Kc = (K + S - 1) / S;
    dim3 grid((N + 63) / 64, (M + 63) / 64, S);
    k_sgemm64<false, true><<<grid, 256>>>(A, lda, B, nullptr, part, 0, M, N, K, Kc);
    int tot = M * N;
    if (relu) k_reduce<true><<<(tot + 255) / 256, 256>>>(part, S, bias, C, ldc, M, N);
    else      k_reduce<false><<<(tot + 255) / 256, 256>>>(part, S, bias, C, ldc, M, N);
}

static void sgemm_small(const float* A, int lda, const float* B, const float* bias,
                        float* C, int ldc, int M, int N, int K, bool relu) {
    dim3 grid((N + 63) / 64, (M + 63) / 64, 1);
    if (relu) k_sgemm64<true, false><<<grid, 256>>>(A, lda, B, bias, C, ldc, M, N, K, K);
    else      k_sgemm64<false, false><<<grid, 256>>>(A, lda, B, bias, C, ldc, M, N, K, K);
}

extern "C" void kernel_launch(void* const* d_in, const int* in_sizes, int n_in,
                              void* d_out, int out_size) {
    const float* x1   = (const float*)d_in[0];
    const int*   ei1  = (const int*)d_in[1];
    const int*   bat1 = (const int*)d_in[2];
    const float* x2   = (const float*)d_in[3];
    const int*   ei2  = (const int*)d_in[4];
    const int*   bat2 = (const int*)d_in[5];
    const float* cell = (const float*)d_in[6];
    const float* Wc1 = (const float*)d_in[7];  const float* bc1 = (const float*)d_in[8];
    const float* Wc2 = (const float*)d_in[9];  const float* bc2 = (const float*)d_in[10];
    const float* Wc3 = (const float*)d_in[11]; const float* bc3 = (const float*)d_in[12];
    const float* Wg1 = (const float*)d_in[13]; const float* bg1 = (const float*)d_in[14];
    const float* Wg2 = (const float*)d_in[15]; const float* bg2 = (const float*)d_in[16];
    const float* Wr1 = (const float*)d_in[17]; const float* br1 = (const float*)d_in[18];
    const float* Wr2 = (const float*)d_in[19]; const float* br2 = (const float*)d_in[20];
    const float* Wr3 = (const float*)d_in[21]; const float* br3 = (const float*)d_in[22];
    const float* Wf1 = (const float*)d_in[23]; const float* bf1 = (const float*)d_in[24];
    const float* Wf2 = (const float*)d_in[25]; const float* bf2 = (const float*)d_in[26];
    const float* Wf3 = (const float*)d_in[27]; const float* bf3 = (const float*)d_in[28];
    const float* Wo  = (const float*)d_in[29]; const float* bo  = (const float*)d_in[30];
    float* out = (float*)d_out;

    float *bufA, *bufB, *dinv, *pool, *xc, *t0, *t1, *part;
    int *work, *offs, *csr;
    cudaGetSymbolAddress((void**)&bufA, g_bufA);
    cudaGetSymbolAddress((void**)&bufB, g_bufB);
    cudaGetSymbolAddress((void**)&work, g_work);
    cudaGetSymbolAddress((void**)&offs, g_offs);
    cudaGetSymbolAddress((void**)&csr,  g_csr);
    cudaGetSymbolAddress((void**)&dinv, g_dinv);
    cudaGetSymbolAddress((void**)&pool, g_pool);
    cudaGetSymbolAddress((void**)&xc,   g_xc);
    cudaGetSymbolAddress((void**)&t0,   g_t0);
    cudaGetSymbolAddress((void**)&t1,   g_t1);
    cudaGetSymbolAddress((void**)&part, g_part);
    int* cnt  = work;
    int* fill = work + N2;

    const int EB2 = (E2 + 255) / 256;
    const int AGGB = (N2 * 32 + 255) / 256;

    // ---- CSR build (combined graph): launches 1-4
    cudaMemsetAsync(work, 0, 2 * N2 * sizeof(int));
    k_count2<<<EB2, 256>>>(ei1, ei2, cnt);
    k_scan_dinv<<<1, 1024>>>(cnt, offs, dinv);
    k_fill2<<<EB2, 256>>>(ei1, ei2, offs, fill, csr);

    // ---- GCN layers (batched M = 40000)
    // launch 5: agg1; launch 6: first node GEMM (gets profiled)
    k_agg<78, 78, 80, 3><<<AGGB, 256>>>(x1, x2, offs, csr, dinv, bufA);
    gemm_node(bufA, 80, Wc1, bc1, bufB, 80, N2, 78, 78, true);
    k_agg<78, 80, 80, 3><<<AGGB, 256>>>(bufB, bufB + (size_t)NN * 80, offs, csr, dinv, bufA);
    gemm_node(bufA, 80, Wc2, bc2, bufB, 160, N2, 156, 78, true);
    k_agg<156, 160, 160, 5><<<AGGB, 256>>>(bufB, bufB + (size_t)NN * 160, offs, csr, dinv, bufA);
    gemm_node(bufA, 160, Wc3, bc3, bufB, 312, N2, 312, 156, true);

    // ---- global max pool -> [2G, 312]
    cudaMemsetAsync(pool, 0, 2 * GG * 312 * sizeof(float));
    int pthreads = (N2 / 32) * 312;
    k_pool<<<(pthreads + 255) / 256, 256>>>(bufB, bat1, bat2, pool);

    // ---- branch MLP batched over both branches (M = 512)
    sgemm_split(pool, 312, Wg1, bg1, t0, 156, 2 * GG, 156, 312, 4, true, part);
    sgemm_split(t0, 156, Wg2, bg2, t1, 128, 2 * GG, 128, 156, 2, false, part);
    k_scatter<<<(2 * GG * 128 + 255) / 256, 256>>>(t1, xc);

    // ---- cell reduction MLP -> xc cols [256..512)
    k_norm<<<GG, 256>>>(cell, t0);
    sgemm_split(t0, 954, Wr1, br1, t1, 2048, GG, 2048, 954, 2, true, part);
    sgemm_split(t1, 2048, Wr2, br2, t0, 512, GG, 512, 2048, 8, true, part);
    sgemm_split(t0, 512, Wr3, br3, xc + 256, 512, GG, 256, 512, 4, true, part);

    // ---- head MLP
    sgemm_split(xc, 512, Wf1, bf1, t0, 1024, GG, 1024, 512, 2, true, part);
    sgemm_split(t0, 1024, Wf2, bf2, t1, 512, GG, 512, 1024, 4, true, part);
    sgemm_split(t1, 512, Wf3, bf3, t0, 128, GG, 128, 512, 4, true, part);
    sgemm_small(t0, 128, Wo, bo, out, 2, GG, 2, 128, false);
}